// round 12
// baseline (speedup 1.0000x reference)
#include <cuda_runtime.h>
#include <cuda_fp16.h>

#define MAXN 100000
#define MAXE 1600000
#define MAXF 128

// ---------------- scratch ----------------
__device__ float  g_bufA[MAXN * MAXF];
__device__ float  g_bufB[MAXN * MAXF];
__device__ __half g_w2thi[128 * 128];   // W2^T hi: [f][k]
__device__ __half g_w2tlo[128 * 128];
__device__ __half g_w3thi[32 * 128];    // W3^T hi: [f][k]
__device__ __half g_w3tlo[32 * 128];
__device__ int    g_deg[MAXN];
__device__ float  g_dinv[MAXN];
__device__ int    g_rowptr[MAXN + 1];
__device__ int    g_fill[MAXN];         // pre-seeded with row starts
__device__ int    g_esrc[MAXE];         // src index only (4B/edge)
__device__ int    g_blocksum[64];

// ---------------- preprocessing ----------------
// blocks [0, EB): degree histogram; blocks [EB, EB+64): W2/W3 hi/lo split (transposed)
__global__ void pre_kernel(const int* __restrict__ dst, int E, int EB,
                           const float* __restrict__ W2, const float* __restrict__ W3) {
    if (blockIdx.x < (unsigned)EB) {
        int e = blockIdx.x * 256 + threadIdx.x;
        if (e < E) atomicAdd(&g_deg[dst[e]], 1);
    } else {
        int i = (blockIdx.x - EB) * 256 + threadIdx.x;
        if (i < 128 * 128) {
            int k = i >> 7, f = i & 127;
            float w = W2[k * 128 + f];
            __half hi = __float2half_rn(w);
            __half lo = __float2half_rn(w - __half2float(hi));
            g_w2thi[f * 128 + k] = hi;
            g_w2tlo[f * 128 + k] = lo;
        }
        if (i < 128 * 32) {
            int k = i >> 5, f = i & 31;
            float w = W3[k * 32 + f];
            __half hi = __float2half_rn(w);
            __half lo = __float2half_rn(w - __half2float(hi));
            g_w3thi[f * 128 + k] = hi;
            g_w3tlo[f * 128 + k] = lo;
        }
    }
}

__global__ void scan1_kernel(int N) {
    const int T = 1024, EL = 4;
    int t = threadIdx.x;
    int base = blockIdx.x * (T * EL) + t * EL;
    int v[EL];
    int s = 0;
#pragma unroll
    for (int j = 0; j < EL; j++) {
        int i = base + j;
        v[j] = (i < N) ? g_deg[i] : 0;
        s += v[j];
    }
    __shared__ int sh[T];
    sh[t] = s;
    __syncthreads();
    for (int o = 1; o < T; o <<= 1) {
        int u = (t >= o) ? sh[t - o] : 0;
        __syncthreads();
        sh[t] += u;
        __syncthreads();
    }
    int run = (t == 0) ? 0 : sh[t - 1];
#pragma unroll
    for (int j = 0; j < EL; j++) {
        int i = base + j;
        if (i < N) g_rowptr[i] = run;
        run += v[j];
    }
    if (t == T - 1) g_blocksum[blockIdx.x] = sh[T - 1];
}

// rowptr offset (in-kernel lookback over <=32 block sums) + dinv + seed g_fill + xs = x*dinv
__global__ void scan3_kernel(const float* __restrict__ x, float* __restrict__ xs,
                             int N, int NB) {
    __shared__ int soff;
    int chunk = (blockIdx.x * 1024) >> 12;   // all 1024 indices share one scan1 chunk
    if (threadIdx.x < 32) {
        int t = threadIdx.x;
        int v = (t < chunk && t < NB) ? g_blocksum[t] : 0;
#pragma unroll
        for (int o = 16; o; o >>= 1) v += __shfl_xor_sync(0xFFFFFFFFu, v, o);
        if (t == 0) soff = v;
    }
    __syncthreads();
    int off = soff;
    int i = blockIdx.x * 1024 + threadIdx.x;
    if (i < N) {
        int d = g_deg[i];
        int rp = g_rowptr[i] + off;
        g_rowptr[i] = rp;
        g_fill[i] = rp;
        float di = rsqrtf((float)d + 1.0f);
        g_dinv[i] = di;
        float2 xv = ((const float2*)x)[i];
        ((float2*)xs)[i] = make_float2(xv.x * di, xv.y * di);
        if (i == N - 1) g_rowptr[N] = rp + d;
    }
}

__global__ void scatter_kernel(const int* __restrict__ src, const int* __restrict__ dst, int E) {
    int e = blockIdx.x * blockDim.x + threadIdx.x;
    if (e >= E) return;
    int pos = atomicAdd(&g_fill[dst[e]], 1);
    g_esrc[pos] = src[e];
}

// ---------------- fp16 convert helper ----------------
__device__ __forceinline__ void cvt8(uint4 v, float* f) {
    float2 a = __half22float2(*(const __half2*)&v.x);
    float2 b = __half22float2(*(const __half2*)&v.y);
    float2 c = __half22float2(*(const __half2*)&v.z);
    float2 d = __half22float2(*(const __half2*)&v.w);
    f[0] = a.x; f[1] = a.y; f[2] = b.x; f[3] = b.y;
    f[4] = c.x; f[5] = c.y; f[6] = d.x; f[7] = d.y;
}

// ---------------- F=128 agg of pre-scaled fp16 -> hi/lo fp16 ----------------
__global__ void __launch_bounds__(128) aggh128hl_kernel(
        const __half* __restrict__ h, __half* __restrict__ outhi,
        __half* __restrict__ outlo, int N) {
    constexpr int TPN = 16;
    int n = blockIdx.x * 8 + threadIdx.x / TPN;
    if (n >= N) return;
    int f8 = threadIdx.x % TPN;
    const uint4* __restrict__ h8 = (const uint4*)h;
    float di = g_dinv[n];
    float acc0[8], acc1[8];
    cvt8(h8[n * TPN + f8], acc0);
#pragma unroll
    for (int i = 0; i < 8; i++) acc1[i] = 0.0f;
    int beg = g_rowptr[n], end = g_rowptr[n + 1];
    int j = beg;
    for (; j + 1 < end; j += 2) {
        int sA = g_esrc[j];
        int sB = g_esrc[j + 1];
        uint4 va = h8[sA * TPN + f8];
        uint4 vb = h8[sB * TPN + f8];
        float ta[8], tb[8];
        cvt8(va, ta); cvt8(vb, tb);
#pragma unroll
        for (int i = 0; i < 8; i++) {
            acc0[i] += ta[i];
            acc1[i] += tb[i];
        }
    }
    if (j < end) {
        uint4 va = h8[g_esrc[j] * TPN + f8];
        float ta[8];
        cvt8(va, ta);
#pragma unroll
        for (int i = 0; i < 8; i++) acc0[i] += ta[i];
    }
    __half hi[8], lo[8];
#pragma unroll
    for (int i = 0; i < 8; i++) {
        float r = (acc0[i] + acc1[i]) * di;
        hi[i] = __float2half_rn(r);
        lo[i] = __float2half_rn(r - __half2float(hi[i]));
    }
    ((uint4*)outhi)[n * TPN + f8] = *(uint4*)hi;
    ((uint4*)outlo)[n * TPN + f8] = *(uint4*)lo;
}

// ---------------- split-fp16 HMMA layer-2 ----------------
#define SB 72
__global__ void __launch_bounds__(128) hmma2_kernel(
        const __half* __restrict__ t2hi, const __half* __restrict__ t2lo,
        const float* __restrict__ b2, __half* __restrict__ x2hi,
        __half* __restrict__ x2lo, int N) {
    __shared__ __half sAhi[64 * SB], sAlo[64 * SB];
    __shared__ __half sBhi[64 * SB], sBlo[64 * SB];
    int tid = threadIdx.x;
    int base = blockIdx.x * 64;
    int fb = blockIdx.y;
    int warp = tid >> 5, lane = tid & 31;
    int wm = (warp >> 1) * 32, wn = (warp & 1) * 32;
    int gr = lane >> 2, gc = lane & 3;

    float c[2][4][4];
#pragma unroll
    for (int t = 0; t < 2; t++)
#pragma unroll
        for (int u = 0; u < 4; u++)
#pragma unroll
            for (int i = 0; i < 4; i++) c[t][u][i] = 0.0f;

    const __half* whi = g_w2thi + fb * 64 * 128;
    const __half* wlo = g_w2tlo + fb * 64 * 128;

    for (int kc = 0; kc < 128; kc += 64) {
        for (int i = tid; i < 64 * 8; i += 128) {
            int r = i >> 3, c8 = i & 7;
            int n = base + r;
            uint4 vh = make_uint4(0, 0, 0, 0), vl = make_uint4(0, 0, 0, 0);
            if (n < N) {
                vh = ((const uint4*)(t2hi + n * 128 + kc))[c8];
                vl = ((const uint4*)(t2lo + n * 128 + kc))[c8];
            }
            *(uint4*)&sAhi[r * SB + c8 * 8] = vh;
            *(uint4*)&sAlo[r * SB + c8 * 8] = vl;
            *(uint4*)&sBhi[r * SB + c8 * 8] = ((const uint4*)(whi + r * 128 + kc))[c8];
            *(uint4*)&sBlo[r * SB + c8 * 8] = ((const uint4*)(wlo + r * 128 + kc))[c8];
        }
        __syncthreads();

        for (int k0 = 0; k0 < 64; k0 += 16) {
            unsigned ah[2][4], al[2][4], bh[4][2], bl[4][2];
#pragma unroll
            for (int t = 0; t < 2; t++) {
                int ro = (wm + t * 16 + gr) * SB + k0 + gc * 2;
                ah[t][0] = *(const unsigned*)&sAhi[ro];
                ah[t][1] = *(const unsigned*)&sAhi[ro + 8 * SB];
                ah[t][2] = *(const unsigned*)&sAhi[ro + 8];
                ah[t][3] = *(const unsigned*)&sAhi[ro + 8 * SB + 8];
                al[t][0] = *(const unsigned*)&sAlo[ro];
                al[t][1] = *(const unsigned*)&sAlo[ro + 8 * SB];
                al[t][2] = *(const unsigned*)&sAlo[ro + 8];
                al[t][3] = *(const unsigned*)&sAlo[ro + 8 * SB + 8];
            }
#pragma unroll
            for (int u = 0; u < 4; u++) {
                int ro = (wn + u * 8 + gr) * SB + k0 + gc * 2;
                bh[u][0] = *(const unsigned*)&sBhi[ro];
                bh[u][1] = *(const unsigned*)&sBhi[ro + 8];
                bl[u][0] = *(const unsigned*)&sBlo[ro];
                bl[u][1] = *(const unsigned*)&sBlo[ro + 8];
            }
#pragma unroll
            for (int t = 0; t < 2; t++)
#pragma unroll
                for (int u = 0; u < 4; u++) {
#define MMA(A0,A1,A2,A3,B0,B1) \
    asm volatile("mma.sync.aligned.m16n8k16.row.col.f32.f16.f16.f32 " \
        "{%0,%1,%2,%3}, {%4,%5,%6,%7}, {%8,%9}, {%0,%1,%2,%3};" \
        : "+f"(c[t][u][0]), "+f"(c[t][u][1]), "+f"(c[t][u][2]), "+f"(c[t][u][3]) \
        : "r"(A0), "r"(A1), "r"(A2), "r"(A3), "r"(B0), "r"(B1))
                    MMA(ah[t][0], ah[t][1], ah[t][2], ah[t][3], bh[u][0], bh[u][1]);
                    MMA(ah[t][0], ah[t][1], ah[t][2], ah[t][3], bl[u][0], bl[u][1]);
                    MMA(al[t][0], al[t][1], al[t][2], al[t][3], bh[u][0], bh[u][1]);
#undef MMA
                }
        }
        __syncthreads();
    }
#pragma unroll
    for (int u = 0; u < 4; u++) {
        int colg = fb * 64 + wn + u * 8 + gc * 2;
        float bv0 = b2[colg], bv1 = b2[colg + 1];
#pragma unroll
        for (int t = 0; t < 2; t++) {
#pragma unroll
            for (int half = 0; half < 2; half++) {
                int r = base + wm + t * 16 + gr + half * 8;
                if (r < N) {
                    float v0 = fmaxf(c[t][u][half * 2 + 0] + bv0, 0.0f);
                    float v1 = fmaxf(c[t][u][half * 2 + 1] + bv1, 0.0f);
                    __half h0 = __float2half_rn(v0);
                    __half h1 = __float2half_rn(v1);
                    __half l0 = __float2half_rn(v0 - __half2float(h0));
                    __half l1 = __float2half_rn(v1 - __half2float(h1));
                    __half2 hp; hp.x = h0; hp.y = h1;
                    __half2 lp; lp.x = l0; lp.y = l1;
                    *(__half2*)&x2hi[r * 128 + colg] = hp;
                    *(__half2*)&x2lo[r * 128 + colg] = lp;
                }
            }
        }
    }
}

// ---------------- split-fp16 HMMA layer-3a: t3s = (x2 * W3) * dinv[row] -> fp16 ----------------
__global__ void __launch_bounds__(128) hmma3_kernel(
        const __half* __restrict__ x2hi, const __half* __restrict__ x2lo,
        __half* __restrict__ t3, int N) {
    __shared__ __half sAhi[64 * SB], sAlo[64 * SB];
    __shared__ __half sBhi[32 * SB], sBlo[32 * SB];
    int tid = threadIdx.x;
    int base = blockIdx.x * 64;
    int warp = tid >> 5, lane = tid & 31;
    int wm = warp * 16;
    int gr = lane >> 2, gc = lane & 3;

    float c[4][4];
#pragma unroll
    for (int u = 0; u < 4; u++)
#pragma unroll
        for (int i = 0; i < 4; i++) c[u][i] = 0.0f;

    for (int kc = 0; kc < 128; kc += 64) {
        for (int i = tid; i < 64 * 8; i += 128) {
            int r = i >> 3, c8 = i & 7;
            int n = base + r;
            uint4 vh = make_uint4(0, 0, 0, 0), vl = make_uint4(0, 0, 0, 0);
            if (n < N) {
                vh = ((const uint4*)(x2hi + n * 128 + kc))[c8];
                vl = ((const uint4*)(x2lo + n * 128 + kc))[c8];
            }
            *(uint4*)&sAhi[r * SB + c8 * 8] = vh;
            *(uint4*)&sAlo[r * SB + c8 * 8] = vl;
        }
        for (int i = tid; i < 32 * 8; i += 128) {
            int r = i >> 3, c8 = i & 7;
            *(uint4*)&sBhi[r * SB + c8 * 8] = ((const uint4*)(g_w3thi + r * 128 + kc))[c8];
            *(uint4*)&sBlo[r * SB + c8 * 8] = ((const uint4*)(g_w3tlo + r * 128 + kc))[c8];
        }
        __syncthreads();

        for (int k0 = 0; k0 < 64; k0 += 16) {
            unsigned ah[4], al[4], bh[4][2], bl[4][2];
            {
                int ro = (wm + gr) * SB + k0 + gc * 2;
                ah[0] = *(const unsigned*)&sAhi[ro];
                ah[1] = *(const unsigned*)&sAhi[ro + 8 * SB];
                ah[2] = *(const unsigned*)&sAhi[ro + 8];
                ah[3] = *(const unsigned*)&sAhi[ro + 8 * SB + 8];
                al[0] = *(const unsigned*)&sAlo[ro];
                al[1] = *(const unsigned*)&sAlo[ro + 8 * SB];
                al[2] = *(const unsigned*)&sAlo[ro + 8];
                al[3] = *(const unsigned*)&sAlo[ro + 8 * SB + 8];
            }
#pragma unroll
            for (int u = 0; u < 4; u++) {
                int ro = (u * 8 + gr) * SB + k0 + gc * 2;
                bh[u][0] = *(const unsigned*)&sBhi[ro];
                bh[u][1] = *(const unsigned*)&sBhi[ro + 8];
                bl[u][0] = *(const unsigned*)&sBlo[ro];
                bl[u][1] = *(const unsigned*)&sBlo[ro + 8];
            }
#pragma unroll
            for (int u = 0; u < 4; u++) {
#define MMA3(A0,A1,A2,A3,B0,B1) \
    asm volatile("mma.sync.aligned.m16n8k16.row.col.f32.f16.f16.f32 " \
        "{%0,%1,%2,%3}, {%4,%5,%6,%7}, {%8,%9}, {%0,%1,%2,%3};" \
        : "+f"(c[u][0]), "+f"(c[u][1]), "+f"(c[u][2]), "+f"(c[u][3]) \
        : "r"(A0), "r"(A1), "r"(A2), "r"(A3), "r"(B0), "r"(B1))
                MMA3(ah[0], ah[1], ah[2], ah[3], bh[u][0], bh[u][1]);
                MMA3(ah[0], ah[1], ah[2], ah[3], bl[u][0], bl[u][1]);
                MMA3(al[0], al[1], al[2], al[3], bh[u][0], bh[u][1]);
#undef MMA3
            }
        }
        __syncthreads();
    }
#pragma unroll
    for (int u = 0; u < 4; u++) {
        int col = u * 8 + gc * 2;
#pragma unroll
        for (int half = 0; half < 2; half++) {
            int r = base + wm + gr + half * 8;
            if (r < N) {
                float di = g_dinv[r];
                __half2 hp;
                hp.x = __float2half_rn(c[u][half * 2 + 0] * di);
                hp.y = __float2half_rn(c[u][half * 2 + 1] * di);
                *(__half2*)&t3[r * 32 + col] = hp;
            }
        }
    }
}

// ---------------- F=32 agg (standalone, layer 3): x3s = relu(dinv*sum + b3)*dinv -> fp16 ----------------
__global__ void __launch_bounds__(128) agg32l3_kernel(
        const __half* __restrict__ h, __half* __restrict__ outv,
        const float* __restrict__ b, int N) {
    constexpr int TPN = 4;
    int n = blockIdx.x * 32 + threadIdx.x / TPN;
    if (n >= N) return;
    int f8 = threadIdx.x % TPN;
    const uint4* __restrict__ h8 = (const uint4*)h;
    float di = g_dinv[n];
    float acc0[8], acc1[8];
    cvt8(h8[n * TPN + f8], acc0);
#pragma unroll
    for (int i = 0; i < 8; i++) acc1[i] = 0.0f;
    int beg = g_rowptr[n], end = g_rowptr[n + 1];
    int j = beg;
    for (; j + 1 < end; j += 2) {
        int sA = g_esrc[j];
        int sB = g_esrc[j + 1];
        uint4 va = h8[sA * TPN + f8];
        uint4 vb = h8[sB * TPN + f8];
        float ta[8], tb[8];
        cvt8(va, ta); cvt8(vb, tb);
#pragma unroll
        for (int i = 0; i < 8; i++) {
            acc0[i] += ta[i];
            acc1[i] += tb[i];
        }
    }
    if (j < end) {
        uint4 va = h8[g_esrc[j] * TPN + f8];
        float ta[8];
        cvt8(va, ta);
#pragma unroll
        for (int i = 0; i < 8; i++) acc0[i] += ta[i];
    }
    const float4 b0 = *reinterpret_cast<const float4*>(b + f8 * 8);
    const float4 b1 = *reinterpret_cast<const float4*>(b + f8 * 8 + 4);
    float r[8];
    r[0] = fmaxf((acc0[0] + acc1[0]) * di + b0.x, 0.f) * di;
    r[1] = fmaxf((acc0[1] + acc1[1]) * di + b0.y, 0.f) * di;
    r[2] = fmaxf((acc0[2] + acc1[2]) * di + b0.z, 0.f) * di;
    r[3] = fmaxf((acc0[3] + acc1[3]) * di + b0.w, 0.f) * di;
    r[4] = fmaxf((acc0[4] + acc1[4]) * di + b1.x, 0.f) * di;
    r[5] = fmaxf((acc0[5] + acc1[5]) * di + b1.y, 0.f) * di;
    r[6] = fmaxf((acc0[6] + acc1[6]) * di + b1.z, 0.f) * di;
    r[7] = fmaxf((acc0[7] + acc1[7]) * di + b1.w, 0.f) * di;
    uint4 o;
    *(__half2*)&o.x = __float22half2_rn(make_float2(r[0], r[1]));
    *(__half2*)&o.y = __float22half2_rn(make_float2(r[2], r[3]));
    *(__half2*)&o.z = __float22half2_rn(make_float2(r[4], r[5]));
    *(__half2*)&o.w = __float22half2_rn(make_float2(r[6], r[7]));
    ((uint4*)outv)[n * TPN + f8] = o;
}

// ---------------- fused layer 4: x4s = relu((dinv*sum x3s) W4 + b4)*dinv -> fp16 ----------------
#define TSS 36
__global__ void __launch_bounds__(128) aggemm4_kernel(
        const __half* __restrict__ h, __half* __restrict__ out,
        const float* __restrict__ W, const float* __restrict__ b, int N) {
    __shared__ float ts[32 * TSS];
    __shared__ float ws[32 * 32];
    __shared__ float bs[32];
    int tid = threadIdx.x;
    for (int i = tid; i < 1024; i += 128) ws[i] = W[i];
    if (tid < 32) bs[tid] = b[tid];
    int nl = tid >> 2, f8 = tid & 3;
    int n = blockIdx.x * 32 + nl;
    bool valid = n < N;
    float acc0[8] = {0, 0, 0, 0, 0, 0, 0, 0};
    float acc1[8] = {0, 0, 0, 0, 0, 0, 0, 0};
    float di = 0.0f;
    if (valid) {
        const uint4* __restrict__ h8 = (const uint4*)h;
        di = g_dinv[n];
        cvt8(h8[n * 4 + f8], acc0);
        int beg = g_rowptr[n], end = g_rowptr[n + 1];
        int j = beg;
        for (; j + 1 < end; j += 2) {
            int sA = g_esrc[j];
            int sB = g_esrc[j + 1];
            uint4 va = h8[sA * 4 + f8];
            uint4 vb = h8[sB * 4 + f8];
            float ta[8], tb[8];
            cvt8(va, ta); cvt8(vb, tb);
#pragma unroll
            for (int i = 0; i < 8; i++) {
                acc0[i] += ta[i];
                acc1[i] += tb[i];
            }
        }
        if (j < end) {
            uint4 va = h8[g_esrc[j] * 4 + f8];
            float ta[8];
            cvt8(va, ta);
#pragma unroll
            for (int i = 0; i < 8; i++) acc0[i] += ta[i];
        }
    }
    float* myts = &ts[nl * TSS + f8 * 8];
#pragma unroll
    for (int i = 0; i < 8; i++) myts[i] = (acc0[i] + acc1[i]) * di;
    __syncthreads();
    // GEMM: thread (nl, f8) computes outputs f8*8..f8*8+7 for node nl
    float acc[8] = {0, 0, 0, 0, 0, 0, 0, 0};
    const float* trow = &ts[nl * TSS];
    for (int k = 0; k < 32; k++) {
        float xv = trow[k];
        const float4 wa = *reinterpret_cast<const float4*>(&ws[k * 32 + f8 * 8]);
        const float4 wb = *reinterpret_cast<const float4*>(&ws[k * 32 + f8 * 8 + 4]);
        acc[0] = fmaf(xv, wa.x, acc[0]); acc[1] = fmaf(xv, wa.y, acc[1]);
        acc[2] = fmaf(xv, wa.z, acc[2]); acc[3] = fmaf(xv, wa.w, acc[3]);
        acc[4] = fmaf(xv, wb.x, acc[4]); acc[5] = fmaf(xv, wb.y, acc[5]);
        acc[6] = fmaf(xv, wb.z, acc[6]); acc[7] = fmaf(xv, wb.w, acc[7]);
    }
    if (valid) {
        float r[8];
#pragma unroll
        for (int i = 0; i < 8; i++)
            r[i] = fmaxf(acc[i] + bs[f8 * 8 + i], 0.0f) * di;
        uint4 o;
        *(__half2*)&o.x = __float22half2_rn(make_float2(r[0], r[1]));
        *(__half2*)&o.y = __float22half2_rn(make_float2(r[2], r[3]));
        *(__half2*)&o.z = __float22half2_rn(make_float2(r[4], r[5]));
        *(__half2*)&o.w = __float22half2_rn(make_float2(r[6], r[7]));
        ((uint4*)out)[n * 4 + f8] = o;
    }
}

// ---------------- fused layer 5 + linear: out[n] = relu((dinv*sum x4s) W5 + b5) . Wl + bl ----------------
__global__ void __launch_bounds__(128) aggemm5l_kernel(
        const __half* __restrict__ h, float* __restrict__ out,
        const float* __restrict__ W, const float* __restrict__ b,
        const float* __restrict__ Wl, const float* __restrict__ bl, int N) {
    __shared__ float ts[32 * TSS];
    __shared__ float ws[32 * 64];
    __shared__ float bs[64];
    __shared__ float wls[64];
    int tid = threadIdx.x;
    for (int i = tid; i < 2048; i += 128) ws[i] = W[i];
    if (tid < 64) { bs[tid] = b[tid]; wls[tid] = Wl[tid]; }
    int nl = tid >> 2, q = tid & 3;
    int n = blockIdx.x * 32 + nl;
    bool valid = n < N;
    float acc0[8] = {0, 0, 0, 0, 0, 0, 0, 0};
    float acc1[8] = {0, 0, 0, 0, 0, 0, 0, 0};
    float di = 0.0f;
    if (valid) {
        const uint4* __restrict__ h8 = (const uint4*)h;
        di = g_dinv[n];
        cvt8(h8[n * 4 + q], acc0);
        int beg = g_rowptr[n], end = g_rowptr[n + 1];
        int j = beg;
        for (; j + 1 < end; j += 2) {
            int sA = g_esrc[j];
            int sB = g_esrc[j + 1];
            uint4 va = h8[sA * 4 + q];
            uint4 vb = h8[sB * 4 + q];
            float ta[8], tb[8];
            cvt8(va, ta); cvt8(vb, tb);
#pragma unroll
            for (int i = 0; i < 8; i++) {
                acc0[i] += ta[i];
                acc1[i] += tb[i];
            }
        }
        if (j < end) {
            uint4 va = h8[g_esrc[j] * 4 + q];
            float ta[8];
            cvt8(va, ta);
#pragma unroll
            for (int i = 0; i < 8; i++) acc0[i] += ta[i];
        }
    }
    float* myts = &ts[nl * TSS + q * 8];
#pragma unroll
    for (int i = 0; i < 8; i++) myts[i] = (acc0[i] + acc1[i]) * di;
    __syncthreads();
    // GEMM: thread (nl,q) computes 16 of 64 outputs, then partial dot with Wl
    float acc[16];
#pragma unroll
    for (int i = 0; i < 16; i++) acc[i] = 0.0f;
    const float* trow = &ts[nl * TSS];
    for (int k = 0; k < 32; k++) {
        float xv = trow[k];
        const float* wr = &ws[k * 64 + q * 16];
#pragma unroll
        for (int i4 = 0; i4 < 4; i4++) {
            const float4 w4 = *reinterpret_cast<const float4*>(wr + i4 * 4);
            acc[i4 * 4 + 0] = fmaf(xv, w4.x, acc[i4 * 4 + 0]);
            acc[i4 * 4 + 1] = fmaf(xv, w4.y, acc[i4 * 4 + 1]);
            acc[i4 * 4 + 2] = fmaf(xv, w4.z, acc[i4 * 4 + 2]);
            acc[i4 * 4 + 3] = fmaf(xv, w4.w, acc[i4 * 4 + 3]);
        }
    }
    float p = 0.0f;
#pragma unroll
    for (int i = 0; i < 16; i++) {
        float x5 = fmaxf(acc[i] + bs[q * 16 + i], 0.0f);
        p = fmaf(x5, wls[q * 16 + i], p);
    }
    p += __shfl_xor_sync(0xFFFFFFFFu, p, 1);
    p += __shfl_xor_sync(0xFFFFFFFFu, p, 2);
    if (q == 0 && valid) out[n] = p + bl[0];
}

// ---------------- layer-1 fused: x1s = relu(agg(xs)*W1 + b1)*dinv -> fp16 ----------------
__global__ void __launch_bounds__(128) l1_kernel(
        const float* __restrict__ xs, const float* __restrict__ W1,
        const float* __restrict__ b1, __half* __restrict__ out, int N) {
    __shared__ float t2s[128];
    __shared__ float sdi[64];
    __shared__ float ws[256];
    __shared__ float bs[128];
    int tid = threadIdx.x;
    ws[tid] = W1[tid];
    ws[128 + tid] = W1[128 + tid];
    bs[tid] = b1[tid];
    int nl = tid >> 1;
    int n = blockIdx.x * 64 + nl;
    int f = tid & 1;
    float acc = 0.0f, di = 0.0f;
    if (n < N) {
        di = g_dinv[n];
        acc = xs[n * 2 + f];
        int beg = g_rowptr[n], end = g_rowptr[n + 1];
        for (int j = beg; j < end; j++)
            acc += xs[g_esrc[j] * 2 + f];
        acc *= di;
    }
    t2s[tid] = acc;
    if (f == 0) sdi[nl] = di;
    __syncthreads();
    float w0 = ws[tid], w1 = ws[128 + tid], bv = bs[tid];
    int nmax = min(64, N - blockIdx.x * 64);
    for (int q = 0; q < nmax; q++) {
        float v = fmaf(t2s[q * 2], w0, fmaf(t2s[q * 2 + 1], w1, bv));
        v = fmaxf(v, 0.0f) * sdi[q];
        out[(blockIdx.x * 64 + q) * 128 + tid] = __float2half_rn(v);
    }
}

// ---------------- launch ----------------
extern "C" void kernel_launch(void* const* d_in, const int* in_sizes, int n_in,
                              void* d_out, int out_size) {
    const float* x  = (const float*)d_in[0];
    const int*   ei = (const int*)d_in[1];
    int wb = n_in - 12;
    const float* W1 = (const float*)d_in[wb + 0];
    const float* b1 = (const float*)d_in[wb + 1];
    const float* W2 = (const float*)d_in[wb + 2];
    const float* b2 = (const float*)d_in[wb + 3];
    const float* W3 = (const float*)d_in[wb + 4];
    const float* b3 = (const float*)d_in[wb + 5];
    const float* W4 = (const float*)d_in[wb + 6];
    const float* b4 = (const float*)d_in[wb + 7];
    const float* W5 = (const float*)d_in[wb + 8];
    const float* b5 = (const float*)d_in[wb + 9];
    const float* Wl = (const float*)d_in[wb + 10];
    const float* bl = (const float*)d_in[wb + 11];
    float* out = (float*)d_out;

    int N = in_sizes[0] / 2;
    int E = in_sizes[1] / 2;
    const int* src = ei;
    const int* dst = ei + E;

    float *bufA, *bufB;
    cudaGetSymbolAddress((void**)&bufA, g_bufA);
    cudaGetSymbolAddress((void**)&bufB, g_bufB);
    float*  xs   = (float*)bufB;
    __half* hx1s = (__half*)bufA;
    __half* t2hi = (__half*)bufB;
    __half* t2lo = (__half*)bufB + MAXN * 128;
    __half* x2hi = (__half*)bufA;
    __half* x2lo = (__half*)bufA + MAXN * 128;
    __half* ht3s = (__half*)bufB;
    __half* hx3s = (__half*)bufB + MAXN * 128;
    __half* hx4s = (__half*)bufB;
    int *degp;
    cudaGetSymbolAddress((void**)&degp, g_deg);

    // ---- build normalized CSR (src-only edges) + weight split ----
    cudaMemsetAsync(degp, 0, N * sizeof(int));
    int EB = (E + 255) / 256;
    pre_kernel<<<EB + 64, 256>>>(dst, E, EB, W2, W3);
    int NB = (N + 4095) / 4096;
    scan1_kernel<<<NB, 1024>>>(N);
    scan3_kernel<<<(N + 1023) / 1024, 1024>>>(x, xs, N, NB);
    scatter_kernel<<<(E + 255) / 256, 256>>>(src, dst, E);

    // ---- layer 1 fused ----
    l1_kernel<<<(N + 63) / 64, 128>>>(xs, W1, b1, hx1s, N);

    // ---- layer 2 ----
    aggh128hl_kernel<<<(N + 7) / 8, 128>>>(hx1s, t2hi, t2lo, N);
    dim3 g2((N + 63) / 64, 2);
    hmma2_kernel<<<g2, 128>>>(t2hi, t2lo, b2, x2hi, x2lo, N);

    // ---- layer 3 ----
    hmma3_kernel<<<(N + 63) / 64, 128>>>(x2hi, x2lo, ht3s, N);
    agg32l3_kernel<<<(N + 31) / 32, 128>>>(ht3s, hx3s, b3, N);

    // ---- layer 4 fused ----
    aggemm4_kernel<<<(N + 31) / 32, 128>>>(hx3s, hx4s, W4, b4, N);

    // ---- layer 5 + linear fused ----
    aggemm5l_kernel<<<(N + 31) / 32, 128>>>(hx4s, out, W5, b5, Wl, bl, N);
}

// round 13
// speedup vs baseline: 1.1342x; 1.1342x over previous
#include <cuda_runtime.h>
#include <cuda_fp16.h>

#define MAXN 100000
#define MAXE 1600000
#define MAXF 128

// ---------------- scratch ----------------
__device__ float  g_bufA[MAXN * MAXF];
__device__ float  g_bufB[MAXN * MAXF];
__device__ __half g_w2thi[128 * 128];   // W2^T hi: [f][k]
__device__ __half g_w2tlo[128 * 128];
__device__ __half g_w3thi[32 * 128];    // W3^T hi: [f][k]
__device__ __half g_w3tlo[32 * 128];
__device__ int    g_deg[MAXN];
__device__ float  g_dinv[MAXN];
__device__ int    g_rowptr[MAXN + 1];
__device__ int    g_fill[MAXN];         // pre-seeded with row starts
__device__ int    g_esrc[MAXE];         // src index only (4B/edge)
__device__ int    g_blocksum[64];

// ---------------- preprocessing ----------------
// blocks [0, EB): degree histogram; blocks [EB, EB+64): W2/W3 hi/lo split (transposed)
__global__ void pre_kernel(const int* __restrict__ dst, int E, int EB,
                           const float* __restrict__ W2, const float* __restrict__ W3) {
    if (blockIdx.x < (unsigned)EB) {
        int e = blockIdx.x * 256 + threadIdx.x;
        if (e < E) atomicAdd(&g_deg[dst[e]], 1);
    } else {
        int i = (blockIdx.x - EB) * 256 + threadIdx.x;
        if (i < 128 * 128) {
            int k = i >> 7, f = i & 127;
            float w = W2[k * 128 + f];
            __half hi = __float2half_rn(w);
            __half lo = __float2half_rn(w - __half2float(hi));
            g_w2thi[f * 128 + k] = hi;
            g_w2tlo[f * 128 + k] = lo;
        }
        if (i < 128 * 32) {
            int k = i >> 5, f = i & 31;
            float w = W3[k * 32 + f];
            __half hi = __float2half_rn(w);
            __half lo = __float2half_rn(w - __half2float(hi));
            g_w3thi[f * 128 + k] = hi;
            g_w3tlo[f * 128 + k] = lo;
        }
    }
}

__global__ void scan1_kernel(int N) {
    const int T = 1024, EL = 4;
    int t = threadIdx.x;
    int base = blockIdx.x * (T * EL) + t * EL;
    int v[EL];
    int s = 0;
#pragma unroll
    for (int j = 0; j < EL; j++) {
        int i = base + j;
        v[j] = (i < N) ? g_deg[i] : 0;
        s += v[j];
    }
    __shared__ int sh[T];
    sh[t] = s;
    __syncthreads();
    for (int o = 1; o < T; o <<= 1) {
        int u = (t >= o) ? sh[t - o] : 0;
        __syncthreads();
        sh[t] += u;
        __syncthreads();
    }
    int run = (t == 0) ? 0 : sh[t - 1];
#pragma unroll
    for (int j = 0; j < EL; j++) {
        int i = base + j;
        if (i < N) g_rowptr[i] = run;
        run += v[j];
    }
    if (t == T - 1) g_blocksum[blockIdx.x] = sh[T - 1];
}

// rowptr offset (in-kernel lookback over <=32 block sums) + dinv + seed g_fill + xs = x*dinv
__global__ void scan3_kernel(const float* __restrict__ x, float* __restrict__ xs,
                             int N, int NB) {
    __shared__ int soff;
    int chunk = (blockIdx.x * 1024) >> 12;   // all 1024 indices share one scan1 chunk
    if (threadIdx.x < 32) {
        int t = threadIdx.x;
        int v = (t < chunk && t < NB) ? g_blocksum[t] : 0;
#pragma unroll
        for (int o = 16; o; o >>= 1) v += __shfl_xor_sync(0xFFFFFFFFu, v, o);
        if (t == 0) soff = v;
    }
    __syncthreads();
    int off = soff;
    int i = blockIdx.x * 1024 + threadIdx.x;
    if (i < N) {
        int d = g_deg[i];
        int rp = g_rowptr[i] + off;
        g_rowptr[i] = rp;
        g_fill[i] = rp;
        float di = rsqrtf((float)d + 1.0f);
        g_dinv[i] = di;
        float2 xv = ((const float2*)x)[i];
        ((float2*)xs)[i] = make_float2(xv.x * di, xv.y * di);
        if (i == N - 1) g_rowptr[N] = rp + d;
    }
}

__global__ void scatter_kernel(const int* __restrict__ src, const int* __restrict__ dst, int E) {
    int e = blockIdx.x * blockDim.x + threadIdx.x;
    if (e >= E) return;
    int pos = atomicAdd(&g_fill[dst[e]], 1);
    g_esrc[pos] = src[e];
}

// ---------------- fp16 convert helper ----------------
__device__ __forceinline__ void cvt8(uint4 v, float* f) {
    float2 a = __half22float2(*(const __half2*)&v.x);
    float2 b = __half22float2(*(const __half2*)&v.y);
    float2 c = __half22float2(*(const __half2*)&v.z);
    float2 d = __half22float2(*(const __half2*)&v.w);
    f[0] = a.x; f[1] = a.y; f[2] = b.x; f[3] = b.y;
    f[4] = c.x; f[5] = c.y; f[6] = d.x; f[7] = d.y;
}

// ---------------- F=128 agg of pre-scaled fp16 -> hi/lo fp16 ----------------
__global__ void __launch_bounds__(128) aggh128hl_kernel(
        const __half* __restrict__ h, __half* __restrict__ outhi,
        __half* __restrict__ outlo, int N) {
    constexpr int TPN = 16;
    int n = blockIdx.x * 8 + threadIdx.x / TPN;
    if (n >= N) return;
    int f8 = threadIdx.x % TPN;
    const uint4* __restrict__ h8 = (const uint4*)h;
    float di = g_dinv[n];
    float acc0[8], acc1[8];
    cvt8(h8[n * TPN + f8], acc0);
#pragma unroll
    for (int i = 0; i < 8; i++) acc1[i] = 0.0f;
    int beg = g_rowptr[n], end = g_rowptr[n + 1];
    int j = beg;
    for (; j + 1 < end; j += 2) {
        int sA = g_esrc[j];
        int sB = g_esrc[j + 1];
        uint4 va = h8[sA * TPN + f8];
        uint4 vb = h8[sB * TPN + f8];
        float ta[8], tb[8];
        cvt8(va, ta); cvt8(vb, tb);
#pragma unroll
        for (int i = 0; i < 8; i++) {
            acc0[i] += ta[i];
            acc1[i] += tb[i];
        }
    }
    if (j < end) {
        uint4 va = h8[g_esrc[j] * TPN + f8];
        float ta[8];
        cvt8(va, ta);
#pragma unroll
        for (int i = 0; i < 8; i++) acc0[i] += ta[i];
    }
    __half hi[8], lo[8];
#pragma unroll
    for (int i = 0; i < 8; i++) {
        float r = (acc0[i] + acc1[i]) * di;
        hi[i] = __float2half_rn(r);
        lo[i] = __float2half_rn(r - __half2float(hi[i]));
    }
    ((uint4*)outhi)[n * TPN + f8] = *(uint4*)hi;
    ((uint4*)outlo)[n * TPN + f8] = *(uint4*)lo;
}

// ---------------- split-fp16 HMMA layer-2 ----------------
#define SB 72
__global__ void __launch_bounds__(128) hmma2_kernel(
        const __half* __restrict__ t2hi, const __half* __restrict__ t2lo,
        const float* __restrict__ b2, __half* __restrict__ x2hi,
        __half* __restrict__ x2lo, int N) {
    __shared__ __half sAhi[64 * SB], sAlo[64 * SB];
    __shared__ __half sBhi[64 * SB], sBlo[64 * SB];
    int tid = threadIdx.x;
    int base = blockIdx.x * 64;
    int fb = blockIdx.y;
    int warp = tid >> 5, lane = tid & 31;
    int wm = (warp >> 1) * 32, wn = (warp & 1) * 32;
    int gr = lane >> 2, gc = lane & 3;

    float c[2][4][4];
#pragma unroll
    for (int t = 0; t < 2; t++)
#pragma unroll
        for (int u = 0; u < 4; u++)
#pragma unroll
            for (int i = 0; i < 4; i++) c[t][u][i] = 0.0f;

    const __half* whi = g_w2thi + fb * 64 * 128;
    const __half* wlo = g_w2tlo + fb * 64 * 128;

    for (int kc = 0; kc < 128; kc += 64) {
        for (int i = tid; i < 64 * 8; i += 128) {
            int r = i >> 3, c8 = i & 7;
            int n = base + r;
            uint4 vh = make_uint4(0, 0, 0, 0), vl = make_uint4(0, 0, 0, 0);
            if (n < N) {
                vh = ((const uint4*)(t2hi + n * 128 + kc))[c8];
                vl = ((const uint4*)(t2lo + n * 128 + kc))[c8];
            }
            *(uint4*)&sAhi[r * SB + c8 * 8] = vh;
            *(uint4*)&sAlo[r * SB + c8 * 8] = vl;
            *(uint4*)&sBhi[r * SB + c8 * 8] = ((const uint4*)(whi + r * 128 + kc))[c8];
            *(uint4*)&sBlo[r * SB + c8 * 8] = ((const uint4*)(wlo + r * 128 + kc))[c8];
        }
        __syncthreads();

        for (int k0 = 0; k0 < 64; k0 += 16) {
            unsigned ah[2][4], al[2][4], bh[4][2], bl[4][2];
#pragma unroll
            for (int t = 0; t < 2; t++) {
                int ro = (wm + t * 16 + gr) * SB + k0 + gc * 2;
                ah[t][0] = *(const unsigned*)&sAhi[ro];
                ah[t][1] = *(const unsigned*)&sAhi[ro + 8 * SB];
                ah[t][2] = *(const unsigned*)&sAhi[ro + 8];
                ah[t][3] = *(const unsigned*)&sAhi[ro + 8 * SB + 8];
                al[t][0] = *(const unsigned*)&sAlo[ro];
                al[t][1] = *(const unsigned*)&sAlo[ro + 8 * SB];
                al[t][2] = *(const unsigned*)&sAlo[ro + 8];
                al[t][3] = *(const unsigned*)&sAlo[ro + 8 * SB + 8];
            }
#pragma unroll
            for (int u = 0; u < 4; u++) {
                int ro = (wn + u * 8 + gr) * SB + k0 + gc * 2;
                bh[u][0] = *(const unsigned*)&sBhi[ro];
                bh[u][1] = *(const unsigned*)&sBhi[ro + 8];
                bl[u][0] = *(const unsigned*)&sBlo[ro];
                bl[u][1] = *(const unsigned*)&sBlo[ro + 8];
            }
#pragma unroll
            for (int t = 0; t < 2; t++)
#pragma unroll
                for (int u = 0; u < 4; u++) {
#define MMA(A0,A1,A2,A3,B0,B1) \
    asm volatile("mma.sync.aligned.m16n8k16.row.col.f32.f16.f16.f32 " \
        "{%0,%1,%2,%3}, {%4,%5,%6,%7}, {%8,%9}, {%0,%1,%2,%3};" \
        : "+f"(c[t][u][0]), "+f"(c[t][u][1]), "+f"(c[t][u][2]), "+f"(c[t][u][3]) \
        : "r"(A0), "r"(A1), "r"(A2), "r"(A3), "r"(B0), "r"(B1))
                    MMA(ah[t][0], ah[t][1], ah[t][2], ah[t][3], bh[u][0], bh[u][1]);
                    MMA(ah[t][0], ah[t][1], ah[t][2], ah[t][3], bl[u][0], bl[u][1]);
                    MMA(al[t][0], al[t][1], al[t][2], al[t][3], bh[u][0], bh[u][1]);
#undef MMA
                }
        }
        __syncthreads();
    }
#pragma unroll
    for (int u = 0; u < 4; u++) {
        int colg = fb * 64 + wn + u * 8 + gc * 2;
        float bv0 = b2[colg], bv1 = b2[colg + 1];
#pragma unroll
        for (int t = 0; t < 2; t++) {
#pragma unroll
            for (int half = 0; half < 2; half++) {
                int r = base + wm + t * 16 + gr + half * 8;
                if (r < N) {
                    float v0 = fmaxf(c[t][u][half * 2 + 0] + bv0, 0.0f);
                    float v1 = fmaxf(c[t][u][half * 2 + 1] + bv1, 0.0f);
                    __half h0 = __float2half_rn(v0);
                    __half h1 = __float2half_rn(v1);
                    __half l0 = __float2half_rn(v0 - __half2float(h0));
                    __half l1 = __float2half_rn(v1 - __half2float(h1));
                    __half2 hp; hp.x = h0; hp.y = h1;
                    __half2 lp; lp.x = l0; lp.y = l1;
                    *(__half2*)&x2hi[r * 128 + colg] = hp;
                    *(__half2*)&x2lo[r * 128 + colg] = lp;
                }
            }
        }
    }
}

// ---------------- split-fp16 HMMA layer-3a: t3s = (x2 * W3) * dinv[row] -> fp16 ----------------
__global__ void __launch_bounds__(128) hmma3_kernel(
        const __half* __restrict__ x2hi, const __half* __restrict__ x2lo,
        __half* __restrict__ t3, int N) {
    __shared__ __half sAhi[64 * SB], sAlo[64 * SB];
    __shared__ __half sBhi[32 * SB], sBlo[32 * SB];
    int tid = threadIdx.x;
    int base = blockIdx.x * 64;
    int warp = tid >> 5, lane = tid & 31;
    int wm = warp * 16;
    int gr = lane >> 2, gc = lane & 3;

    float c[4][4];
#pragma unroll
    for (int u = 0; u < 4; u++)
#pragma unroll
        for (int i = 0; i < 4; i++) c[u][i] = 0.0f;

    for (int kc = 0; kc < 128; kc += 64) {
        for (int i = tid; i < 64 * 8; i += 128) {
            int r = i >> 3, c8 = i & 7;
            int n = base + r;
            uint4 vh = make_uint4(0, 0, 0, 0), vl = make_uint4(0, 0, 0, 0);
            if (n < N) {
                vh = ((const uint4*)(x2hi + n * 128 + kc))[c8];
                vl = ((const uint4*)(x2lo + n * 128 + kc))[c8];
            }
            *(uint4*)&sAhi[r * SB + c8 * 8] = vh;
            *(uint4*)&sAlo[r * SB + c8 * 8] = vl;
        }
        for (int i = tid; i < 32 * 8; i += 128) {
            int r = i >> 3, c8 = i & 7;
            *(uint4*)&sBhi[r * SB + c8 * 8] = ((const uint4*)(g_w3thi + r * 128 + kc))[c8];
            *(uint4*)&sBlo[r * SB + c8 * 8] = ((const uint4*)(g_w3tlo + r * 128 + kc))[c8];
        }
        __syncthreads();

        for (int k0 = 0; k0 < 64; k0 += 16) {
            unsigned ah[4], al[4], bh[4][2], bl[4][2];
            {
                int ro = (wm + gr) * SB + k0 + gc * 2;
                ah[0] = *(const unsigned*)&sAhi[ro];
                ah[1] = *(const unsigned*)&sAhi[ro + 8 * SB];
                ah[2] = *(const unsigned*)&sAhi[ro + 8];
                ah[3] = *(const unsigned*)&sAhi[ro + 8 * SB + 8];
                al[0] = *(const unsigned*)&sAlo[ro];
                al[1] = *(const unsigned*)&sAlo[ro + 8 * SB];
                al[2] = *(const unsigned*)&sAlo[ro + 8];
                al[3] = *(const unsigned*)&sAlo[ro + 8 * SB + 8];
            }
#pragma unroll
            for (int u = 0; u < 4; u++) {
                int ro = (u * 8 + gr) * SB + k0 + gc * 2;
                bh[u][0] = *(const unsigned*)&sBhi[ro];
                bh[u][1] = *(const unsigned*)&sBhi[ro + 8];
                bl[u][0] = *(const unsigned*)&sBlo[ro];
                bl[u][1] = *(const unsigned*)&sBlo[ro + 8];
            }
#pragma unroll
            for (int u = 0; u < 4; u++) {
#define MMA3(A0,A1,A2,A3,B0,B1) \
    asm volatile("mma.sync.aligned.m16n8k16.row.col.f32.f16.f16.f32 " \
        "{%0,%1,%2,%3}, {%4,%5,%6,%7}, {%8,%9}, {%0,%1,%2,%3};" \
        : "+f"(c[u][0]), "+f"(c[u][1]), "+f"(c[u][2]), "+f"(c[u][3]) \
        : "r"(A0), "r"(A1), "r"(A2), "r"(A3), "r"(B0), "r"(B1))
                MMA3(ah[0], ah[1], ah[2], ah[3], bh[u][0], bh[u][1]);
                MMA3(ah[0], ah[1], ah[2], ah[3], bl[u][0], bl[u][1]);
                MMA3(al[0], al[1], al[2], al[3], bh[u][0], bh[u][1]);
#undef MMA3
            }
        }
        __syncthreads();
    }
#pragma unroll
    for (int u = 0; u < 4; u++) {
        int col = u * 8 + gc * 2;
#pragma unroll
        for (int half = 0; half < 2; half++) {
            int r = base + wm + gr + half * 8;
            if (r < N) {
                float di = g_dinv[r];
                __half2 hp;
                hp.x = __float2half_rn(c[u][half * 2 + 0] * di);
                hp.y = __float2half_rn(c[u][half * 2 + 1] * di);
                *(__half2*)&t3[r * 32 + col] = hp;
            }
        }
    }
}

// ---------------- F=32 agg of pre-scaled fp16: out = f(dinv*(sum+self)) ----------------
template <bool BIAS, bool RELU, bool OUT_HALF, bool PRESCALE>
__global__ void __launch_bounds__(128) aggh32_kernel(
        const __half* __restrict__ h, void* __restrict__ outv,
        const float* __restrict__ b, int N) {
    constexpr int TPN = 4;
    int n = blockIdx.x * 32 + threadIdx.x / TPN;
    if (n >= N) return;
    int f8 = threadIdx.x % TPN;
    const uint4* __restrict__ h8 = (const uint4*)h;
    float di = g_dinv[n];
    float acc0[8], acc1[8];
    cvt8(h8[n * TPN + f8], acc0);
#pragma unroll
    for (int i = 0; i < 8; i++) acc1[i] = 0.0f;
    int beg = g_rowptr[n], end = g_rowptr[n + 1];
    int j = beg;
    for (; j + 1 < end; j += 2) {
        int sA = g_esrc[j];
        int sB = g_esrc[j + 1];
        uint4 va = h8[sA * TPN + f8];
        uint4 vb = h8[sB * TPN + f8];
        float ta[8], tb[8];
        cvt8(va, ta); cvt8(vb, tb);
#pragma unroll
        for (int i = 0; i < 8; i++) {
            acc0[i] += ta[i];
            acc1[i] += tb[i];
        }
    }
    if (j < end) {
        uint4 va = h8[g_esrc[j] * TPN + f8];
        float ta[8];
        cvt8(va, ta);
#pragma unroll
        for (int i = 0; i < 8; i++) acc0[i] += ta[i];
    }
    float r[8];
#pragma unroll
    for (int i = 0; i < 8; i++) r[i] = (acc0[i] + acc1[i]) * di;
    if (BIAS) {
        const float4 b0 = *reinterpret_cast<const float4*>(b + f8 * 8);
        const float4 b1 = *reinterpret_cast<const float4*>(b + f8 * 8 + 4);
        r[0] += b0.x; r[1] += b0.y; r[2] += b0.z; r[3] += b0.w;
        r[4] += b1.x; r[5] += b1.y; r[6] += b1.z; r[7] += b1.w;
    }
    if (RELU) {
#pragma unroll
        for (int i = 0; i < 8; i++) r[i] = fmaxf(r[i], 0.0f);
    }
    if (PRESCALE) {
#pragma unroll
        for (int i = 0; i < 8; i++) r[i] *= di;
    }
    if constexpr (OUT_HALF) {
        uint4 o;
        *(__half2*)&o.x = __float22half2_rn(make_float2(r[0], r[1]));
        *(__half2*)&o.y = __float22half2_rn(make_float2(r[2], r[3]));
        *(__half2*)&o.z = __float22half2_rn(make_float2(r[4], r[5]));
        *(__half2*)&o.w = __float22half2_rn(make_float2(r[6], r[7]));
        ((uint4*)outv)[n * TPN + f8] = o;
    } else {
        float* outf = (float*)outv;
        *reinterpret_cast<float4*>(outf + n * 32 + f8 * 8) =
            make_float4(r[0], r[1], r[2], r[3]);
        *reinterpret_cast<float4*>(outf + n * 32 + f8 * 8 + 4) =
            make_float4(r[4], r[5], r[6], r[7]);
    }
}

// ---------------- generic GEMM (scalar FFMA); PRESCALE multiplies output by dinv[n] ----------------
template <int K, int F, int NPG, bool BIAS, bool RELU, bool OUT_HALF, bool PRESCALE>
__global__ void __launch_bounds__(128) gemm_kernel(
        const float* __restrict__ in, const float* __restrict__ W,
        const float* __restrict__ b, void* __restrict__ outv, int N) {
    constexpr int GROUPS = 128 / F;
    constexpr int NT = NPG * GROUPS;
    __shared__ float sx[NT * K];
    int base = blockIdx.x * NT;
    for (int i = threadIdx.x; i < NT * K; i += 128) {
        int r = i / K, c = i % K;
        int n = base + r;
        sx[i] = (n < N) ? in[n * K + c] : 0.0f;
    }
    __syncthreads();
    int f = threadIdx.x % F;
    int g = threadIdx.x / F;
    float acc[NPG];
#pragma unroll
    for (int j = 0; j < NPG; j++) acc[j] = 0.0f;
    for (int k = 0; k < K; k += 4) {
        float w0 = W[(k + 0) * F + f];
        float w1 = W[(k + 1) * F + f];
        float w2 = W[(k + 2) * F + f];
        float w3 = W[(k + 3) * F + f];
#pragma unroll
        for (int j = 0; j < NPG; j++) {
            const float4 x4 = *reinterpret_cast<const float4*>(&sx[(g * NPG + j) * K + k]);
            acc[j] = fmaf(x4.x, w0, acc[j]);
            acc[j] = fmaf(x4.y, w1, acc[j]);
            acc[j] = fmaf(x4.z, w2, acc[j]);
            acc[j] = fmaf(x4.w, w3, acc[j]);
        }
    }
    float bv = BIAS ? b[f] : 0.0f;
#pragma unroll
    for (int j = 0; j < NPG; j++) {
        int n = base + g * NPG + j;
        if (n < N) {
            float v = acc[j] + bv;
            if (RELU) v = fmaxf(v, 0.0f);
            if (PRESCALE) v *= g_dinv[n];
            if constexpr (OUT_HALF)
                ((__half*)outv)[n * F + f] = __float2half_rn(v);
            else
                ((float*)outv)[n * F + f] = v;
        }
    }
}

// ---------------- layer-1 fused: x1s = relu(agg(xs)*W1 + b1)*dinv -> fp16 ----------------
__global__ void __launch_bounds__(128) l1_kernel(
        const float* __restrict__ xs, const float* __restrict__ W1,
        const float* __restrict__ b1, __half* __restrict__ out, int N) {
    __shared__ float t2s[128];
    __shared__ float sdi[64];
    __shared__ float ws[256];
    __shared__ float bs[128];
    int tid = threadIdx.x;
    ws[tid] = W1[tid];
    ws[128 + tid] = W1[128 + tid];
    bs[tid] = b1[tid];
    int nl = tid >> 1;
    int n = blockIdx.x * 64 + nl;
    int f = tid & 1;
    float acc = 0.0f, di = 0.0f;
    if (n < N) {
        di = g_dinv[n];
        acc = xs[n * 2 + f];
        int beg = g_rowptr[n], end = g_rowptr[n + 1];
        for (int j = beg; j < end; j++)
            acc += xs[g_esrc[j] * 2 + f];
        acc *= di;
    }
    t2s[tid] = acc;
    if (f == 0) sdi[nl] = di;
    __syncthreads();
    float w0 = ws[tid], w1 = ws[128 + tid], bv = bs[tid];
    int nmax = min(64, N - blockIdx.x * 64);
    for (int q = 0; q < nmax; q++) {
        float v = fmaf(t2s[q * 2], w0, fmaf(t2s[q * 2 + 1], w1, bv));
        v = fmaxf(v, 0.0f) * sdi[q];
        out[(blockIdx.x * 64 + q) * 128 + tid] = __float2half_rn(v);
    }
}

// ---------------- fused layer 5 + linear ----------------
__global__ void __launch_bounds__(128) gemm5l_kernel(
        const float* __restrict__ in, const float* __restrict__ W5,
        const float* __restrict__ b5, const float* __restrict__ Wl,
        const float* __restrict__ bl, float* __restrict__ out, int N) {
    __shared__ float sx[16 * 32];
    __shared__ float red[4][8];
    int tid = threadIdx.x;
    int base = blockIdx.x * 16;
    for (int i = tid; i < 16 * 32; i += 128) {
        int r = i >> 5, c = i & 31;
        int n = base + r;
        sx[i] = (n < N) ? in[n * 32 + c] : 0.0f;
    }
    __syncthreads();
    int f = tid & 63, g = tid >> 6;
    float acc[8];
#pragma unroll
    for (int j = 0; j < 8; j++) acc[j] = 0.0f;
    for (int k = 0; k < 32; k += 4) {
        float w0 = W5[(k + 0) * 64 + f];
        float w1 = W5[(k + 1) * 64 + f];
        float w2 = W5[(k + 2) * 64 + f];
        float w3 = W5[(k + 3) * 64 + f];
#pragma unroll
        for (int j = 0; j < 8; j++) {
            const float4 x4 = *reinterpret_cast<const float4*>(&sx[(g * 8 + j) * 32 + k]);
            acc[j] = fmaf(x4.x, w0, acc[j]);
            acc[j] = fmaf(x4.y, w1, acc[j]);
            acc[j] = fmaf(x4.z, w2, acc[j]);
            acc[j] = fmaf(x4.w, w3, acc[j]);
        }
    }
    float bv = b5[f], wl = Wl[f];
    float p[8];
#pragma unroll
    for (int j = 0; j < 8; j++)
        p[j] = fmaxf(acc[j] + bv, 0.0f) * wl;
#pragma unroll
    for (int o = 16; o; o >>= 1) {
#pragma unroll
        for (int j = 0; j < 8; j++)
            p[j] += __shfl_xor_sync(0xFFFFFFFFu, p[j], o);
    }
    int w = tid >> 5, lane = tid & 31;
    if (lane == 0) {
#pragma unroll
        for (int j = 0; j < 8; j++) red[w][j] = p[j];
    }
    __syncthreads();
    if (tid < 16) {
        int gs = tid >> 3, j = tid & 7;
        int n = base + gs * 8 + j;
        if (n < N) out[n] = red[gs * 2][j] + red[gs * 2 + 1][j] + bl[0];
    }
}

// ---------------- launch ----------------
extern "C" void kernel_launch(void* const* d_in, const int* in_sizes, int n_in,
                              void* d_out, int out_size) {
    const float* x  = (const float*)d_in[0];
    const int*   ei = (const int*)d_in[1];
    int wb = n_in - 12;
    const float* W1 = (const float*)d_in[wb + 0];
    const float* b1 = (const float*)d_in[wb + 1];
    const float* W2 = (const float*)d_in[wb + 2];
    const float* b2 = (const float*)d_in[wb + 3];
    const float* W3 = (const float*)d_in[wb + 4];
    const float* b3 = (const float*)d_in[wb + 5];
    const float* W4 = (const float*)d_in[wb + 6];
    const float* b4 = (const float*)d_in[wb + 7];
    const float* W5 = (const float*)d_in[wb + 8];
    const float* b5 = (const float*)d_in[wb + 9];
    const float* Wl = (const float*)d_in[wb + 10];
    const float* bl = (const float*)d_in[wb + 11];
    float* out = (float*)d_out;

    int N = in_sizes[0] / 2;
    int E = in_sizes[1] / 2;
    const int* src = ei;
    const int* dst = ei + E;

    float *bufA, *bufB;
    cudaGetSymbolAddress((void**)&bufA, g_bufA);
    cudaGetSymbolAddress((void**)&bufB, g_bufB);
    float*  xs   = (float*)bufB;
    __half* hx1s = (__half*)bufA;
    __half* t2hi = (__half*)bufB;
    __half* t2lo = (__half*)bufB + MAXN * 128;
    __half* x2hi = (__half*)bufA;
    __half* x2lo = (__half*)bufA + MAXN * 128;
    __half* ht3s = (__half*)bufB;
    __half* hx3s = (__half*)bufB + MAXN * 128;
    __half* hx4s = (__half*)bufB;
    int *degp;
    cudaGetSymbolAddress((void**)&degp, g_deg);

    // ---- build normalized CSR (src-only edges) + weight split ----
    cudaMemsetAsync(degp, 0, N * sizeof(int));
    int EB = (E + 255) / 256;
    pre_kernel<<<EB + 64, 256>>>(dst, E, EB, W2, W3);
    int NB = (N + 4095) / 4096;
    scan1_kernel<<<NB, 1024>>>(N);
    scan3_kernel<<<(N + 1023) / 1024, 1024>>>(x, xs, N, NB);
    scatter_kernel<<<(E + 255) / 256, 256>>>(src, dst, E);

    // ---- layer 1 fused: x1s = relu(agg(xs) W1 + b1)*dinv -> fp16 ----
    l1_kernel<<<(N + 63) / 64, 128>>>(xs, W1, b1, hx1s, N);

    // ---- layer 2: t2 = dinv*(sum x1s) -> hi/lo ; x2 = relu(t2 W2 + b2) -> hi/lo ----
    aggh128hl_kernel<<<(N + 7) / 8, 128>>>(hx1s, t2hi, t2lo, N);
    dim3 g2((N + 63) / 64, 2);
    hmma2_kernel<<<g2, 128>>>(t2hi, t2lo, b2, x2hi, x2lo, N);

    // ---- layer 3: t3s = (x2 W3)*dinv -> fp16 ; x3s = relu(dinv*sum + b3)*dinv -> fp16 ----
    hmma3_kernel<<<(N + 63) / 64, 128>>>(x2hi, x2lo, ht3s, N);
    aggh32_kernel<true, true, true, true><<<(N + 31) / 32, 128>>>(ht3s, hx3s, b3, N);

    // ---- layer 4: t4 = dinv*sum(x3s) -> fp32 ; x4s = relu(t4 W4 + b4)*dinv -> fp16 ----
    aggh32_kernel<false, false, false, false><<<(N + 31) / 32, 128>>>(hx3s, bufA, nullptr, N);
    gemm_kernel<32, 32, 8, true, true, true, true><<<(N + 31) / 32, 128>>>(bufA, W4, b4, hx4s, N);

    // ---- layer 5: t5 = dinv*sum(x4s) -> fp32 ; out = relu(t5 W5 + b5) . Wl + bl ----
    aggh32_kernel<false, false, false, false><<<(N + 31) / 32, 128>>>(hx4s, bufA, nullptr, N);
    gemm5l_kernel<<<(N + 15) / 16, 128>>>(bufA, W5, b5, Wl, bl, out, N);
}